// round 16
// baseline (speedup 1.0000x reference)
#include <cuda_runtime.h>
#include <cuda_fp16.h>
#include <cstdint>

typedef unsigned long long ull;

// Problem constants
#define BATCH 64
#define LSEQ  400
#define CIN   500
#define DMODEL 128
#define NHEAD 8
#define HDIM  16
#define MROWS (BATCH*LSEQ)          // 25600
#define LPAD  (LSEQ+4)              // 404
#define KCONV 2500
#define CONV_CHUNKS 80              // K padded to 2560, BK=32
#define GEMM_CHUNKS 4               // K=128
#define CONV_BWORDS (CONV_CHUNKS*2048)
#define GEMM_BWORDS (GEMM_CHUNKS*2048)

// ---------------- scratch ----------------------------------------------------
__device__ __half g_xph[BATCH*LPAD*CIN + 4096];   // padded input, fp16 hi only
__device__ float g_pe[LSEQ*DMODEL];
__device__ float g_h  [MROWS*DMODEL];             // residual stream (fp32)
__device__ float g_tmp[MROWS*DMODEL];
// fp16-pair intermediates (half2-packed words, [MROWS][64])
__device__ uint32_t g_lnh[MROWS*64],  g_lnl[MROWS*64];
__device__ uint32_t g_dwh[MROWS*64],  g_dwl[MROWS*64];   // also K out at attn
__device__ uint32_t g_ath[MROWS*64],  g_atl[MROWS*64];
__device__ uint32_t g_ffh[MROWS*64],  g_ffl[MROWS*64];   // also Q out at attn
__device__ uint32_t g_vh [MROWS*64],  g_vl [MROWS*64];   // V out at attn

// pre-split weights in HMMA B-fragment order, fp16x2 words (hi plane only)
__device__ uint32_t g_bh[CONV_BWORDS + 10*GEMM_BWORDS];

// ---------------- helpers ----------------------------------------------------
__device__ __forceinline__ uint32_t smem_u32(const void* p){
    uint32_t a;
    asm("{ .reg .u64 t; cvta.to.shared.u64 t, %1; cvt.u32.u64 %0, t; }"
        : "=r"(a) : "l"(p));
    return a;
}
__device__ __forceinline__ void split2(float f0, float f1, uint32_t& h, uint32_t& l){
    __half h0 = __float2half_rn(f0);
    __half h1 = __float2half_rn(f1);
    float r0 = f0 - __half2float(h0);
    float r1 = f1 - __half2float(h1);
    __half l0 = __float2half_rn(r0);
    __half l1 = __float2half_rn(r1);
    unsigned short hu0 = *(unsigned short*)&h0, hu1 = *(unsigned short*)&h1;
    unsigned short lu0 = *(unsigned short*)&l0, lu1 = *(unsigned short*)&l1;
    h = (uint32_t)hu0 | ((uint32_t)hu1 << 16);
    l = (uint32_t)lu0 | ((uint32_t)lu1 << 16);
}
__device__ __forceinline__ uint32_t pack_hi2(float f0, float f1){
    __half h0 = __float2half_rn(f0);
    __half h1 = __float2half_rn(f1);
    unsigned short hu0 = *(unsigned short*)&h0, hu1 = *(unsigned short*)&h1;
    return (uint32_t)hu0 | ((uint32_t)hu1 << 16);
}
__device__ __forceinline__ void mma_f16(float* d, const uint32_t* a, const uint32_t* b){
    asm volatile(
        "mma.sync.aligned.m16n8k16.row.col.f32.f16.f16.f32 "
        "{%0,%1,%2,%3}, {%4,%5,%6,%7}, {%8,%9}, {%0,%1,%2,%3};"
        : "+f"(d[0]), "+f"(d[1]), "+f"(d[2]), "+f"(d[3])
        : "r"(a[0]), "r"(a[1]), "r"(a[2]), "r"(a[3]), "r"(b[0]), "r"(b[1]));
}
__device__ __forceinline__ void ldm_x4(uint32_t* r, uint32_t addr){
    asm volatile("ldmatrix.sync.aligned.m8n8.x4.shared.b16 {%0,%1,%2,%3}, [%4];"
        : "=r"(r[0]), "=r"(r[1]), "=r"(r[2]), "=r"(r[3]) : "r"(addr));
}
__device__ __forceinline__ void ldm_x2(uint32_t* r, uint32_t addr){
    asm volatile("ldmatrix.sync.aligned.m8n8.x2.shared.b16 {%0,%1}, [%2];"
        : "=r"(r[0]), "=r"(r[1]) : "r"(addr));
}
__device__ __forceinline__ void cp16(uint32_t daddr, const void* gptr){
    asm volatile("cp.async.cg.shared.global [%0], [%1], 16;"
                 :: "r"(daddr), "l"(gptr) : "memory");
}
__device__ __forceinline__ void cp8(uint32_t daddr, const void* gptr){
    asm volatile("cp.async.ca.shared.global [%0], [%1], 8;"
                 :: "r"(daddr), "l"(gptr) : "memory");
}
__device__ __forceinline__ void cp_commit(){
    asm volatile("cp.async.commit_group;" ::: "memory");
}
__device__ __forceinline__ void cp_wait0(){
    asm volatile("cp.async.wait_group 0;" ::: "memory");
}
__device__ __forceinline__ void cp_wait1(){
    asm volatile("cp.async.wait_group 1;" ::: "memory");
}

// ---------------- pad x -> fp16 hi plane [B,404,500] -------------------------
__global__ void __launch_bounds__(256) pad_kernel(const float* __restrict__ x){
    int idx = blockIdx.x*256 + threadIdx.x;
    if (idx >= BATCH*LPAD*(CIN/4)) return;
    int c4 = idx % (CIN/4);
    int rest = idx / (CIN/4);
    int lp = rest % LPAD;
    int b  = rest / LPAD;
    int l = lp - 2;
    float4 v = make_float4(0.f,0.f,0.f,0.f);
    if (l >= 0 && l < LSEQ) v = ((const float4*)x)[(b*LSEQ + l)*(CIN/4) + c4];
    uint32_t h0 = pack_hi2(v.x, v.y);
    uint32_t h1 = pack_hi2(v.z, v.w);
    long u2 = (long)rest*125 + c4;
    ((uint2*)g_xph)[u2] = make_uint2(h0, h1);
}

// ---------------- positional encoding table ---------------------------------
__global__ void __launch_bounds__(256) pe_kernel(){
    int idx = blockIdx.x*256 + threadIdx.x;
    if (idx >= LSEQ*DMODEL) return;
    int l = idx / DMODEL;
    int d = idx % DMODEL;
    int j = d & ~1;
    float div = expf(-(float)j * (logf(10000.f)/(float)DMODEL));
    float ang = (float)l * div;
    g_pe[idx] = (d & 1) ? cosf(ang) : sinf(ang);
}

// ---------------- weight prep into HMMA B-fragment order (fp16 hi) -----------
__global__ void __launch_bounds__(256) prep_w_kernel(
    const float* __restrict__ w_init, const float* __restrict__ w_pw,
    const float* __restrict__ wq, const float* __restrict__ wk,
    const float* __restrict__ wv, const float* __restrict__ wo,
    const float* __restrict__ w1, const float* __restrict__ w2)
{
    int flat = blockIdx.x*256 + threadIdx.x;
    const float* W; int K, ch, w2i;
    if (flat < CONV_BWORDS){
        W = w_init; K = KCONV;
        ch = flat >> 11; w2i = flat & 2047;
    } else {
        int rem = flat - CONV_BWORDS;
        int m = rem >> 13;
        int w2g = rem & 8191;
        ch = w2g >> 11; w2i = w2g & 2047;
        K = DMODEL;
        switch (m){
            case 0: case 1: case 2: case 3: W = w_pw + m*DMODEL*DMODEL; break;
            case 4: W = wq; break; case 5: W = wk; break;
            case 6: W = wv; break; case 7: W = wo; break;
            case 8: W = w1; break; default: W = w2; break;
        }
    }
    int j    = w2i & 1;
    int lane = (w2i >> 1) & 31;
    int snt  = w2i >> 6;
    int nt   = snt & 15;
    int s    = snt >> 4;
    int n  = nt*8 + (lane >> 2);
    int k2 = (lane & 3) + j*4 + s*8 + ch*16;
    int k  = 2*k2;
    float v0 = (k   < K) ? W[(long)k    *DMODEL + n] : 0.f;
    float v1 = (k+1 < K) ? W[(long)(k+1)*DMODEL + n] : 0.f;
    g_bh[flat] = pack_hi2(v0, v1);
}

// ---------------- 3-stage pipelined HMMA fp16 GEMM, register-resident B ------
// BM=64, 256 threads. A through smem (3-stage cp.async + ldmatrix).
// B is LDG'd directly into a register double buffer (fragment order in gmem,
// identical for all CTAs -> L1-resident). No B smem at all.
// NPA=1 (conv): Ah*Bh.  NPA=2 (dense): Ah*Bh + Al*Bh.
template<int KCHUNKS, bool CONV, int NPA, bool OUTF16>
__global__ void __launch_bounds__(256) gemm_mma(
    const __half* __restrict__ Ah, const __half* __restrict__ Al,
    const uint32_t* __restrict__ Bhi,
    const float* __restrict__ bias, const float* __restrict__ res,
    float* __restrict__ C, uint32_t* __restrict__ Ch, uint32_t* __restrict__ Cl,
    int relu_flag, int res_flag)
{
    constexpr int ABYTES = 64*80;      // one plane, one stage (80B row stride)

    extern __shared__ char smem[];
    uint32_t aBase = smem_u32(smem);

    int t = threadIdx.x, lane = t & 31, wid = t >> 5;
    int m0 = blockIdx.x * 64;
    int wm = wid & 1, wn = wid >> 1;         // 2 x 4 warp grid

    int arow = t >> 2, aq = t & 3;
    long abase;
    if (CONV){
        int m = m0 + arow; int b = m / LSEQ; int l = m - b*LSEQ;
        abase = (long)(b*LPAD + l) * CIN;
    } else {
        abase = (long)(m0 + arow) * DMODEL;
    }
    uint32_t aDstRow = (uint32_t)arow*80 + (uint32_t)aq*16;

    // B fragment uint2 indices for this thread (per chunk: 8 frags)
    int bidx0[8];
    #pragma unroll
    for (int s = 0; s < 2; s++)
        #pragma unroll
        for (int nt = 0; nt < 4; nt++)
            bidx0[s*4+nt] = ((s*16 + wn*4 + nt)*32 + lane);

    float d[2][4][4];
    #pragma unroll
    for (int a=0;a<2;a++)
        #pragma unroll
        for (int b=0;b<4;b++)
            #pragma unroll
            for (int c=0;c<4;c++) d[a][b][c] = 0.f;

    int rowl = lane & 15, ksel = lane >> 4;

    const uint2* Bw = (const uint2*)Bhi;

    auto load_chunkA = [&](int ch, int stage){
        if (CONV){
            const char* gp = (const char*)(Ah + abase + ch*32 + aq*8);
            uint32_t dst = aBase + (uint32_t)(stage*NPA)*ABYTES + aDstRow;
            cp8(dst,     gp);
            cp8(dst + 8, gp + 8);
        } else {
            cp16(aBase + (uint32_t)(stage*NPA)*ABYTES + aDstRow,
                 Ah + abase + ch*32 + aq*8);
            if (NPA == 2)
                cp16(aBase + (uint32_t)(stage*NPA + 1)*ABYTES + aDstRow,
                     Al + abase + ch*32 + aq*8);
        }
        cp_commit();
    };

    load_chunkA(0, 0);
    if (KCHUNKS > 1) load_chunkA(1, 1);

    // B chunk 0 into cur regs
    uint2 bcur[8], bnext[8];
    #pragma unroll
    for (int i = 0; i < 8; i++) bcur[i] = __ldg(Bw + bidx0[i]);

    int st = 0;
    for (int ch = 0; ch < KCHUNKS; ch++){
        if (ch + 1 < KCHUNKS) cp_wait1(); else cp_wait0();
        __syncthreads();
        if (ch + 2 < KCHUNKS){
            int s2 = st + 2; if (s2 >= 3) s2 -= 3;
            load_chunkA(ch + 2, s2);
        }
        // prefetch B(ch+1) into regs (latency hidden by compute below)
        if (ch + 1 < KCHUNKS){
            long boff = (long)(ch + 1)*1024;
            #pragma unroll
            for (int i = 0; i < 8; i++) bnext[i] = __ldg(Bw + boff + bidx0[i]);
        }

        #pragma unroll
        for (int s = 0; s < 2; s++){
            uint32_t ah[2][4], al[2][4];
            #pragma unroll
            for (int mt2 = 0; mt2 < 2; mt2++){
                int mt = wm*2 + mt2;
                uint32_t aaddr = aBase + (uint32_t)(st*NPA)*ABYTES
                               + (uint32_t)(mt*16 + rowl)*80 + (s*2 + ksel)*16;
                ldm_x4(ah[mt2], aaddr);
                if (NPA == 2) ldm_x4(al[mt2], aaddr + ABYTES);
            }
            #pragma unroll
            for (int nt = 0; nt < 4; nt++){
                const uint32_t* bh = (const uint32_t*)&bcur[s*4+nt];
                #pragma unroll
                for (int mt2 = 0; mt2 < 2; mt2++){
                    mma_f16(d[mt2][nt], ah[mt2], bh);
                    if (NPA == 2)
                        mma_f16(d[mt2][nt], al[mt2], bh);
                }
            }
        }
        #pragma unroll
        for (int i = 0; i < 8; i++) bcur[i] = bnext[i];
        st = (st + 1 == 3) ? 0 : st + 1;
    }

    // epilogue
    int g = lane >> 2, t_ = lane & 3;
    #pragma unroll
    for (int mt2 = 0; mt2 < 2; mt2++){
        int rbase = m0 + wm*32 + mt2*16 + g;
        #pragma unroll
        for (int hf = 0; hf < 2; hf++){
            int row = rbase + hf*8;
            const float* pe = CONV ? (g_pe + (long)(row % LSEQ)*DMODEL) : (const float*)0;
            #pragma unroll
            for (int nt = 0; nt < 4; nt++){
                int col = wn*32 + nt*8 + t_*2;
                float v0 = d[mt2][nt][hf*2+0];
                float v1 = d[mt2][nt][hf*2+1];
                float2 bb = *(const float2*)(bias + col);
                v0 += bb.x; v1 += bb.y;
                if (CONV){
                    float2 p = *(const float2*)(pe + col);
                    v0 += p.x; v1 += p.y;
                }
                if (relu_flag){ v0 = fmaxf(v0, 0.f); v1 = fmaxf(v1, 0.f); }
                if (res_flag){
                    float2 r = *(const float2*)(res + (long)row*DMODEL + col);
                    v0 += r.x; v1 += r.y;
                }
                if (OUTF16){
                    uint32_t hh, ll;
                    split2(v0, v1, hh, ll);
                    long oi = (long)row*64 + (col >> 1);
                    Ch[oi] = hh; Cl[oi] = ll;
                } else {
                    *(float2*)(C + (long)row*DMODEL + col) = make_float2(v0, v1);
                }
            }
        }
    }
}

// ---------------- layernorm: one warp per row -> fp16 pair -------------------
__global__ void __launch_bounds__(256) ln_kernel(
    const float* __restrict__ x, const float* __restrict__ g,
    const float* __restrict__ b, uint32_t* __restrict__ yh,
    uint32_t* __restrict__ yl)
{
    int t = threadIdx.x;
    int row = blockIdx.x*8 + (t >> 5);
    int lane = t & 31;
    float4 v = ((const float4*)x)[row*32 + lane];
    float s  = v.x + v.y + v.z + v.w;
    float sq = v.x*v.x + v.y*v.y + v.z*v.z + v.w*v.w;
    #pragma unroll
    for (int o = 16; o; o >>= 1){
        s  += __shfl_xor_sync(0xffffffffu, s,  o);
        sq += __shfl_xor_sync(0xffffffffu, sq, o);
    }
    float mean = s * (1.f/DMODEL);
    float var  = sq * (1.f/DMODEL) - mean*mean;
    float rs = rsqrtf(var + 1e-5f);
    float4 gg = ((const float4*)g)[lane];
    float4 bb = ((const float4*)b)[lane];
    float o0 = (v.x-mean)*rs*gg.x + bb.x;
    float o1 = (v.y-mean)*rs*gg.y + bb.y;
    float o2 = (v.z-mean)*rs*gg.z + bb.z;
    float o3 = (v.w-mean)*rs*gg.w + bb.w;
    uint32_t h0,l0,h1,l1;
    split2(o0,o1,h0,l0); split2(o2,o3,h1,l1);
    ((uint2*)yh)[row*32 + lane] = make_uint2(h0,h1);
    ((uint2*)yl)[row*32 + lane] = make_uint2(l0,l1);
}

// ---------------- fused layernorm + depthwise conv k=7 -> fp16 pair ----------
__global__ void __launch_bounds__(256) lndw_kernel(
    const float* __restrict__ x, const float* __restrict__ g,
    const float* __restrict__ b, const float* __restrict__ wdw,
    const float* __restrict__ bdw, uint32_t* __restrict__ yh,
    uint32_t* __restrict__ yl)
{
    __shared__ float4 sln[56][32];
    int blk = blockIdx.x;
    int bidx = blk >> 3, lb = blk & 7;
    int l0 = lb * 50;
    int t = threadIdx.x, wid = t >> 5, lane = t & 31;

    float4 gg = ((const float4*)g)[lane];
    float4 bb = ((const float4*)b)[lane];

    #pragma unroll
    for (int rr = 0; rr < 7; rr++){
        int r = wid + rr*8;
        int l = l0 - 3 + r;
        float4 o4 = make_float4(0.f,0.f,0.f,0.f);
        if (l >= 0 && l < LSEQ){
            float4 v = ((const float4*)x)[(bidx*LSEQ + l)*32 + lane];
            float s  = v.x + v.y + v.z + v.w;
            float sq = v.x*v.x + v.y*v.y + v.z*v.z + v.w*v.w;
            #pragma unroll
            for (int o = 16; o; o >>= 1){
                s  += __shfl_xor_sync(0xffffffffu, s,  o);
                sq += __shfl_xor_sync(0xffffffffu, sq, o);
            }
            float mean = s * (1.f/DMODEL);
            float var  = sq * (1.f/DMODEL) - mean*mean;
            float rs = rsqrtf(var + 1e-5f);
            o4.x = (v.x-mean)*rs*gg.x + bb.x;
            o4.y = (v.y-mean)*rs*gg.y + bb.y;
            o4.z = (v.z-mean)*rs*gg.z + bb.z;
            o4.w = (v.w-mean)*rs*gg.w + bb.w;
        }
        sln[r][lane] = o4;
    }
    __syncthreads();

    float4 wv[7];
    #pragma unroll
    for (int tap = 0; tap < 7; tap++) wv[tap] = ((const float4*)wdw)[tap*32 + lane];
    float4 bias4 = ((const float4*)bdw)[lane];

    #pragma unroll
    for (int rr = 0; rr < 7; rr++){
        int r = wid + rr*8;
        if (r < 50){
            float4 acc = bias4;
            #pragma unroll
            for (int tap = 0; tap < 7; tap++){
                float4 xv = sln[r + tap][lane];
                acc.x += xv.x*wv[tap].x; acc.y += xv.y*wv[tap].y;
                acc.z += xv.z*wv[tap].z; acc.w += xv.w*wv[tap].w;
            }
            uint32_t h0,lo0,h1,lo1;
            split2(acc.x,acc.y,h0,lo0); split2(acc.z,acc.w,h1,lo1);
            long u2 = (long)(bidx*LSEQ + l0 + r)*32 + lane;
            ((uint2*)yh)[u2] = make_uint2(h0,h1);
            ((uint2*)yl)[u2] = make_uint2(lo0,lo1);
        }
    }
}

// ---------------- HMMA flash-attention ---------------------------------------
// One CTA per (b,h), 256 threads (8 warps). Q 2-pass (Qh+Ql vs Kh), P fp16,
// PV vs transposed V (Vt). No max-subtraction (scores bounded ~|2|).
#define SM_QH 0
#define SM_QL 19200
#define SM_KH 38400
#define SM_VT 57600
#define SM_VS (57600+13056)
#define SM_ATTN (SM_VS + 12800)      // 83456
__global__ void __launch_bounds__(256) attn_mma_kernel(
    const uint32_t* __restrict__ Qh, const uint32_t* __restrict__ Ql,
    const uint32_t* __restrict__ Kh, const uint32_t* __restrict__ Vh,
    uint32_t* __restrict__ Oh, uint32_t* __restrict__ Ol)
{
    extern __shared__ char sm[];
    uint32_t base = smem_u32(sm);
    uint32_t bQh = base + SM_QH, bQl = base + SM_QL;
    uint32_t bKh = base + SM_KH, bVt = base + SM_VT, bVs = base + SM_VS;

    int t = threadIdx.x, lane = t & 31, wid = t >> 5;
    int bh = blockIdx.x;
    int b = bh >> 3, hd = bh & 7;
    long rowbase = (long)(b*LSEQ)*64 + hd*8;

    for (int i = t; i < 800; i += 256){
        int r = i >> 1, half = i & 1;
        long gw = rowbase + (long)r*64 + half*4;
        uint32_t doff = (uint32_t)r*48 + half*16;
        cp16(bQh + doff, Qh + gw);
        cp16(bQl + doff, Ql + gw);
        cp16(bKh + doff, Kh + gw);
        cp16(bVs + (uint32_t)r*32 + half*16, Vh + gw);
    }
    cp_commit(); cp_wait0();
    __syncthreads();

    for (int i = t; i < 3200; i += 256){
        int r = i >> 3, w8 = i & 7;
        uint32_t val = *(uint32_t*)(sm + SM_VS + r*32 + w8*4);
        __half lo = *(__half*)&val;
        __half hi = *((__half*)&val + 1);
        *(__half*)(sm + SM_VT + (2*w8  )*816 + r*2) = lo;
        *(__half*)(sm + SM_VT + (2*w8+1)*816 + r*2) = hi;
    }
    __syncthreads();

    int rowl = lane & 15, ksel = lane >> 4;
    int l8 = lane & 7, lh = (lane >> 3) & 1;
    int g = lane >> 2, t_ = lane & 3;

    for (int qt = wid; qt < 25; qt += 8){
        uint32_t aqh[4], aql[4];
        uint32_t qoff = (uint32_t)(qt*16 + rowl)*48 + ksel*16;
        ldm_x4(aqh, bQh + qoff);
        ldm_x4(aql, bQl + qoff);

        float o0[4] = {0,0,0,0}, o1[4] = {0,0,0,0};
        float rs0 = 0.f, rs1 = 0.f;

        for (int jb = 0; jb < 25; jb++){
            float s0[4] = {0,0,0,0}, s1[4] = {0,0,0,0};
            uint32_t bk[2];
            ldm_x2(bk, bKh + (uint32_t)(jb*16 + l8)*48 + lh*16);
            mma_f16(s0, aqh, bk);
            mma_f16(s0, aql, bk);
            ldm_x2(bk, bKh + (uint32_t)(jb*16 + 8 + l8)*48 + lh*16);
            mma_f16(s1, aqh, bk);
            mma_f16(s1, aql, bk);

            float e00 = __expf(s0[0]*0.25f), e01 = __expf(s0[1]*0.25f);
            float e02 = __expf(s0[2]*0.25f), e03 = __expf(s0[3]*0.25f);
            float e10 = __expf(s1[0]*0.25f), e11 = __expf(s1[1]*0.25f);
            float e12 = __expf(s1[2]*0.25f), e13 = __expf(s1[3]*0.25f);
            rs0 += e00 + e01 + e10 + e11;
            rs1 += e02 + e03 + e12 + e13;

            uint32_t pa[4];
            pa[0] = pack_hi2(e00, e01);
            pa[1] = pack_hi2(e02, e03);
            pa[2] = pack_hi2(e10, e11);
            pa[3] = pack_hi2(e12, e13);

            uint32_t bv[2];
            ldm_x2(bv, bVt + (uint32_t)l8*816 + (uint32_t)jb*32 + lh*16);
            mma_f16(o0, pa, bv);
            ldm_x2(bv, bVt + (uint32_t)(8 + l8)*816 + (uint32_t)jb*32 + lh*16);
            mma_f16(o1, pa, bv);
        }

        rs0 += __shfl_xor_sync(0xffffffffu, rs0, 1);
        rs0 += __shfl_xor_sync(0xffffffffu, rs0, 2);
        rs1 += __shfl_xor_sync(0xffffffffu, rs1, 1);
        rs1 += __shfl_xor_sync(0xffffffffu, rs1, 2);
        float i0 = 1.f / rs0, i1 = 1.f / rs1;

        long base0 = rowbase + (long)(qt*16 + g)*64;
        long base1 = base0 + 8*64;
        uint32_t hh, ll;
        split2(o0[0]*i0, o0[1]*i0, hh, ll); Oh[base0 + t_]   = hh; Ol[base0 + t_]   = ll;
        split2(o1[0]*i0, o1[1]*i0, hh, ll); Oh[base0 + 4+t_] = hh; Ol[base0 + 4+t_] = ll;
        split2(o0[2]*i1, o0[3]*i1, hh, ll); Oh[base1 + t_]   = hh; Ol[base1 + t_]   = ll;
        split2(o1[2]*i1, o1[3]*i1, hh, ll); Oh[base1 + 4+t_] = hh; Ol[base1 + 4+t_] = ll;
    }
}

// ---------------- host orchestration ----------------------------------------
#define SMEM_CONV (3*64*80)                // 15360 B (A only)
#define SMEM_GEMM (3*2*64*80)              // 30720 B (A hi+lo)

extern "C" void kernel_launch(void* const* d_in, const int* in_sizes, int n_in,
                              void* d_out, int out_size)
{
    const float* x      = (const float*)d_in[0];
    const float* w_init = (const float*)d_in[1];
    const float* b_init = (const float*)d_in[2];
    const float* ln_cg  = (const float*)d_in[3];
    const float* ln_cb  = (const float*)d_in[4];
    const float* w_dw   = (const float*)d_in[5];
    const float* b_dw   = (const float*)d_in[6];
    const float* w_pw   = (const float*)d_in[7];
    const float* b_pw   = (const float*)d_in[8];
    const float* ln_ag  = (const float*)d_in[9];
    const float* ln_ab  = (const float*)d_in[10];
    const float* wq     = (const float*)d_in[11];
    const float* bq     = (const float*)d_in[12];
    const float* wk     = (const float*)d_in[13];
    const float* bk     = (const float*)d_in[14];
    const float* wv     = (const float*)d_in[15];
    const float* bv     = (const float*)d_in[16];
    const float* wo     = (const float*)d_in[17];
    const float* bo     = (const float*)d_in[18];
    const float* ln_fg  = (const float*)d_in[19];
    const float* ln_fb  = (const float*)d_in[20];
    const float* w1     = (const float*)d_in[21];
    const float* b1     = (const float*)d_in[22];
    const float* w2     = (const float*)d_in[23];
    const float* b2     = (const float*)d_in[24];

    __half *xph;
    float *h, *tmp;
    uint32_t *lnh, *lnl, *dwh, *dwl, *ath, *atl, *ffh, *ffl, *vh, *vl, *bh;
    cudaGetSymbolAddress((void**)&xph, g_xph);
    cudaGetSymbolAddress((void**)&h,   g_h);
    cudaGetSymbolAddress((void**)&tmp, g_tmp);
    cudaGetSymbolAddress((void**)&lnh, g_lnh);
    cudaGetSymbolAddress((void**)&lnl, g_lnl);
    cudaGetSymbolAddress((void**)&dwh, g_dwh);
    cudaGetSymbolAddress((void**)&dwl, g_dwl);
    cudaGetSymbolAddress((void**)&ath, g_ath);
    cudaGetSymbolAddress((void**)&atl, g_atl);
    cudaGetSymbolAddress((void**)&ffh, g_ffh);
    cudaGetSymbolAddress((void**)&ffl, g_ffl);
    cudaGetSymbolAddress((void**)&vh,  g_vh);
    cudaGetSymbolAddress((void**)&vl,  g_vl);
    cudaGetSymbolAddress((void**)&bh,  g_bh);

    cudaFuncSetAttribute(gemm_mma<CONV_CHUNKS, true, 1, false>,
        cudaFuncAttributeMaxDynamicSharedMemorySize, SMEM_CONV);
    cudaFuncSetAttribute(gemm_mma<GEMM_CHUNKS, false, 2, false>,
        cudaFuncAttributeMaxDynamicSharedMemorySize, SMEM_GEMM);
    cudaFuncSetAttribute(gemm_mma<GEMM_CHUNKS, false, 2, true>,
        cudaFuncAttributeMaxDynamicSharedMemorySize, SMEM_GEMM);
    cudaFuncSetAttribute(attn_mma_kernel,
        cudaFuncAttributeMaxDynamicSharedMemorySize, SM_ATTN);

    // 1) pad+split x, posenc, weight prep
    pad_kernel<<<(BATCH*LPAD*(CIN/4) + 255)/256, 256>>>(x);
    pe_kernel<<<(LSEQ*DMODEL + 255)/256, 256>>>();
    prep_w_kernel<<<(CONV_BWORDS + 10*GEMM_BWORDS)/256, 256>>>(
        w_init, w_pw, wq, wk, wv, wo, w1, w2);

    // 2) init conv (implicit GEMM, 1-pass fp16, reg-B) + posenc -> h
    gemm_mma<CONV_CHUNKS, true, 1, false><<<MROWS/64, 256, SMEM_CONV>>>(
        xph, nullptr, bh, b_init, nullptr, h, nullptr, nullptr, 0, 0);

    #define GW(m) (bh + CONV_BWORDS + (m)*GEMM_BWORDS)

    // 3) 4x depthwise-separable conv blocks
    for (int i = 0; i < 4; i++){
        lndw_kernel<<<BATCH*8, 256>>>(h, ln_cg + i*DMODEL, ln_cb + i*DMODEL,
                                      w_dw + i*7*DMODEL, b_dw + i*DMODEL, dwh, dwl);
        gemm_mma<GEMM_CHUNKS, false, 2, false><<<MROWS/64, 256, SMEM_GEMM>>>(
            (const __half*)dwh, (const __half*)dwl, GW(i),
            b_pw + i*DMODEL, h, h, nullptr, nullptr, 1, 1);
    }

    // 4) attention (QKV emitted as fp16 pairs; attention all-HMMA)
    ln_kernel<<<MROWS/8, 256>>>(h, ln_ag, ln_ab, lnh, lnl);
    gemm_mma<GEMM_CHUNKS, false, 2, true><<<MROWS/64, 256, SMEM_GEMM>>>(
        (const __half*)lnh, (const __half*)lnl, GW(4), bq, nullptr, nullptr, ffh, ffl, 0, 0);
    gemm_mma<GEMM_CHUNKS, false, 2, true><<<MROWS/64, 256, SMEM_GEMM>>>(
        (const __half*)lnh, (const __half*)lnl, GW(5), bk, nullptr, nullptr, dwh, dwl, 0, 0);
    gemm_mma<GEMM_CHUNKS, false, 2, true><<<MROWS/64, 256, SMEM_GEMM>>>(
        (const __half*)lnh, (const __half*)lnl, GW(6), bv, nullptr, nullptr, vh, vl, 0, 0);
    attn_mma_kernel<<<BATCH*NHEAD, 256, SM_ATTN>>>(ffh, ffl, dwh, vh, ath, atl);
    gemm_mma<GEMM_CHUNKS, false, 2, false><<<MROWS/64, 256, SMEM_GEMM>>>(
        (const __half*)ath, (const __half*)atl, GW(7), bo, h, tmp, nullptr, nullptr, 0, 1);

    // 5) FFN -> d_out
    ln_kernel<<<MROWS/8, 256>>>(tmp, ln_fg, ln_fb, lnh, lnl);
    gemm_mma<GEMM_CHUNKS, false, 2, true><<<MROWS/64, 256, SMEM_GEMM>>>(
        (const __half*)lnh, (const __half*)lnl, GW(8), b1, nullptr, nullptr, ffh, ffl, 1, 0);
    gemm_mma<GEMM_CHUNKS, false, 2, false><<<MROWS/64, 256, SMEM_GEMM>>>(
        (const __half*)ffh, (const __half*)ffl, GW(9), b2, tmp, (float*)d_out, nullptr, nullptr, 0, 1);
}